// round 8
// baseline (speedup 1.0000x reference)
#include <cuda_runtime.h>
#include <cstdint>

// ===========================================================================
// Scratch (__device__ globals; no allocation allowed)
// ===========================================================================
__device__ float g_a1[32u * 128u * 128u * 64u];   // conv1 out NHWC
__device__ float g_a2[32u * 64u * 64u * 128u];    // conv2 out NHWC
__device__ float g_a3[32u * 32u * 32u * 256u];    // conv3 out NHWC
__device__ float g_zf[8192u * 256u];              // conv4 out NHWC == zf
__device__ float g_wt2[128u * 1024u];             // w2 as [co][tap*CI+ci]
__device__ float g_wt3[256u * 2048u];
__device__ float g_wt4[256u * 4096u];
__device__ float g_cbnorm[8192];
__device__ unsigned long long g_min[8192];

// ===========================================================================
// mma.sync tf32 helpers (sm_80+ features; valid on plain sm_100 target)
// ===========================================================================
__device__ __forceinline__ void split1(float v, uint32_t& h, uint32_t& l) {
    uint32_t hu;
    asm("cvt.rna.tf32.f32 %0, %1;" : "=r"(hu) : "f"(v));
    float lf = v - __uint_as_float(hu);
    uint32_t lu;
    asm("cvt.rna.tf32.f32 %0, %1;" : "=r"(lu) : "f"(lf));
    h = hu; l = lu;
}

__device__ __forceinline__ void mma8(float* d, const uint32_t* a, const uint32_t* b) {
    asm volatile(
        "mma.sync.aligned.m16n8k8.row.col.f32.tf32.tf32.f32 "
        "{%0,%1,%2,%3}, {%4,%5,%6,%7}, {%8,%9}, {%0,%1,%2,%3};"
        : "+f"(d[0]), "+f"(d[1]), "+f"(d[2]), "+f"(d[3])
        : "r"(a[0]), "r"(a[1]), "r"(a[2]), "r"(a[3]), "r"(b[0]), "r"(b[1]));
}

// SMEM buffer layout (floats): per buffer AH[4096] AL[4096] BH[4096] BL[4096].
// A plane index: ((s*8 + mblk)*32 + lane)*4 + slot   (4 x 8 x 32 x 4)
// B plane index: ((s*16 + nblk)*32 + lane)*2 + slot  (4 x 16 x 32 x 2)
static constexpr int BUF_FLOATS = 16384;
static constexpr int GEMM_SMEM = (128 + 2 * BUF_FLOATS) * 4;   // 131584 bytes

// Compute one K=32 chunk from hi/lo planes. Warp tile 32x32 (2 m-blocks, 4 n-blocks).
__device__ __forceinline__ void compute_chunk(const float* buf, int wm, int wn, int lane,
                                              float acc[2][4][4]) {
    const float* AH = buf;
    const float* AL = buf + 4096;
    const float* BH = buf + 8192;
    const float* BL = buf + 12288;
#pragma unroll
    for (int s = 0; s < 4; s++) {
        uint4 ah[2], al[2];
        uint2 bh[4], bl[4];
#pragma unroll
        for (int i = 0; i < 2; i++) {
            int idx = ((s * 8 + wm * 2 + i) * 32 + lane) * 4;
            ah[i] = *reinterpret_cast<const uint4*>(AH + idx);
            al[i] = *reinterpret_cast<const uint4*>(AL + idx);
        }
#pragma unroll
        for (int j = 0; j < 4; j++) {
            int idx = ((s * 16 + wn * 4 + j) * 32 + lane) * 2;
            bh[j] = *reinterpret_cast<const uint2*>(BH + idx);
            bl[j] = *reinterpret_cast<const uint2*>(BL + idx);
        }
#pragma unroll
        for (int i = 0; i < 2; i++)
#pragma unroll
            for (int j = 0; j < 4; j++) {
                mma8(acc[i][j], &ah[i].x, &bh[j].x);
                mma8(acc[i][j], &al[i].x, &bh[j].x);
                mma8(acc[i][j], &ah[i].x, &bl[j].x);
            }
    }
}

// Split 4 A values and store into hi/lo planes (one float4 each).
__device__ __forceinline__ void stsA_s(float* AH, float* AL, int idx, const float* pa4) {
    uint4 h, l;
    split1(pa4[0], h.x, l.x);
    split1(pa4[1], h.y, l.y);
    split1(pa4[2], h.z, l.z);
    split1(pa4[3], h.w, l.w);
    *reinterpret_cast<uint4*>(AH + idx) = h;
    *reinterpret_cast<uint4*>(AL + idx) = l;
}
__device__ __forceinline__ void stsB_s(float* BH, float* BL, int idx, float v0, float v1) {
    uint2 h, l;
    split1(v0, h.x, l.x);
    split1(v1, h.y, l.y);
    *reinterpret_cast<uint2*>(BH + idx) = h;
    *reinterpret_cast<uint2*>(BL + idx) = l;
}

// ===========================================================================
// Weight transpose: w[co][ci][kh][kw] -> wT[co][ (kh*4+kw)*CI + ci ]
// ===========================================================================
__global__ void wtrans_kernel(const float* __restrict__ w, float* __restrict__ wT,
                              int CI, int CO) {
    int id = blockIdx.x * 256 + threadIdx.x;
    int K = CI * 16;
    if (id >= CO * K) return;
    int co = id / K;
    int r = id % K;
    int tap = r / CI;
    int ci = r % CI;
    wT[id] = w[(co * CI + ci) * 16 + tap];
}

// ===========================================================================
// Conv1: CI=3, k=4 s=2 p=1 + bias + ReLU. NCHW in -> NHWC out.
// ===========================================================================
__global__ __launch_bounds__(256) void conv1_nhwc(const float* __restrict__ x,
                                                  const float* __restrict__ w,
                                                  const float* __restrict__ b,
                                                  float* __restrict__ out) {
    __shared__ __align__(16) float ws[48][64];
    __shared__ float sb[64];
    int tid = threadIdx.x;
    for (int i = tid; i < 3072; i += 256) {
        int tap = i >> 6, co = i & 63;
        ws[tap][co] = w[co * 48 + tap];
    }
    if (tid < 64) sb[tid] = b[tid];
    __syncthreads();

    int p = blockIdx.x * 128 + (tid >> 1);
    int half = tid & 1;
    int n = p >> 14;
    int rp = p & 16383;
    int ho = rp >> 7, wo = rp & 127;
    int hb = 2 * ho - 1, wb = 2 * wo - 1;
    const float* xb = x + (size_t)n * 3 * 65536;

    float acc[32];
#pragma unroll
    for (int c = 0; c < 32; c++) acc[c] = sb[half * 32 + c];

    for (int ci = 0; ci < 3; ci++) {
        const float* xc = xb + ci * 65536;
        for (int kh = 0; kh < 4; kh++) {
            int hi = hb + kh;
            if ((unsigned)hi >= 256u) continue;
            const float* xr = xc + hi * 256;
            for (int kw = 0; kw < 4; kw++) {
                int wi = wb + kw;
                if ((unsigned)wi >= 256u) continue;
                float v = __ldg(xr + wi);
                const float4* wr = reinterpret_cast<const float4*>(&ws[ci * 16 + kh * 4 + kw][half * 32]);
#pragma unroll
                for (int c4 = 0; c4 < 8; c4++) {
                    float4 wv = wr[c4];
                    acc[c4 * 4 + 0] = fmaf(v, wv.x, acc[c4 * 4 + 0]);
                    acc[c4 * 4 + 1] = fmaf(v, wv.y, acc[c4 * 4 + 1]);
                    acc[c4 * 4 + 2] = fmaf(v, wv.z, acc[c4 * 4 + 2]);
                    acc[c4 * 4 + 3] = fmaf(v, wv.w, acc[c4 * 4 + 3]);
                }
            }
        }
    }
    float* op = out + (size_t)p * 64 + half * 32;
#pragma unroll
    for (int c4 = 0; c4 < 8; c4++) {
        float4 v;
        v.x = fmaxf(acc[c4 * 4 + 0], 0.f);
        v.y = fmaxf(acc[c4 * 4 + 1], 0.f);
        v.z = fmaxf(acc[c4 * 4 + 2], 0.f);
        v.w = fmaxf(acc[c4 * 4 + 3], 0.f);
        reinterpret_cast<float4*>(op)[c4] = v;
    }
}

// ===========================================================================
// Tensor-core implicit-GEMM conv (k=4 s=2 p=1) + bias + ReLU, NHWC->NHWC.
// Block 128x128, K = CI*16 chunked by 32; 512 threads, 16 warps, warp 32x32.
// 3xTF32 via mma.sync; hi/lo split done at fill time into smem planes.
// ===========================================================================
template <int CI, int CO, int HI, int WI>
__global__ __launch_bounds__(512) void conv_mma(const float* __restrict__ in,
                                                const float* __restrict__ wT,
                                                const float* __restrict__ bias,
                                                float* __restrict__ out) {
    constexpr int HO = HI / 2, WO = WI / 2;
    constexpr int K = CI * 16;
    constexpr int NCH = K / 32;
    extern __shared__ __align__(16) float smem[];
    float* aux = smem;

    int tid = threadIdx.x, lane = tid & 31, wid = tid >> 5;
    int wm = wid >> 2, wn = wid & 3;
    int rowBase = blockIdx.x * 128;
    int co0 = blockIdx.y * 128;

    if (tid < 128) aux[tid] = bias[co0 + tid];

    // --- A fill (warps 0-7): warp wid = m-block; 2 pixel rows per thread ---
    int rA0 = rowBase + wid * 16 + (lane >> 2);
    int rA1 = rA0 + 8;
    int n0 = rA0 / (HO * WO), rp0 = rA0 % (HO * WO);
    int n1 = rA1 / (HO * WO), rp1 = rA1 % (HO * WO);
    int hb0 = 2 * (rp0 / WO) - 1, wb0 = 2 * (rp0 % WO) - 1;
    int hb1 = 2 * (rp1 / WO) - 1, wb1 = 2 * (rp1 % WO) - 1;
    size_t ab0 = (size_t)n0 * HI * WI * CI;
    size_t ab1 = (size_t)n1 * HI * WI * CI;

    // --- B fill (all 16 warps): warp wid = n-block; 1 weight row per thread ---
    size_t wro = (size_t)(co0 + wid * 8 + (lane >> 2)) * K + (lane & 3);

    float pa[16], pb[8];
    auto loadA = [&](int kk) {
        int kk32 = kk * 32;
        int tap = kk32 / CI, ci0 = kk32 % CI;
        int kh = tap >> 2, kw = tap & 3;
        int hi0 = hb0 + kh, wi0 = wb0 + kw;
        int hi1 = hb1 + kh, wi1 = wb1 + kw;
        bool ok0 = (unsigned)hi0 < (unsigned)HI && (unsigned)wi0 < (unsigned)WI;
        bool ok1 = (unsigned)hi1 < (unsigned)HI && (unsigned)wi1 < (unsigned)WI;
        const float* p0 = in + ab0 + ((size_t)hi0 * WI + wi0) * CI + ci0 + (lane & 3);
        const float* p1 = in + ab1 + ((size_t)hi1 * WI + wi1) * CI + ci0 + (lane & 3);
#pragma unroll
        for (int s = 0; s < 4; s++) {
            pa[s * 4 + 0] = ok0 ? __ldg(p0 + s * 8) : 0.f;
            pa[s * 4 + 1] = ok1 ? __ldg(p1 + s * 8) : 0.f;
            pa[s * 4 + 2] = ok0 ? __ldg(p0 + s * 8 + 4) : 0.f;
            pa[s * 4 + 3] = ok1 ? __ldg(p1 + s * 8 + 4) : 0.f;
        }
    };
    auto loadB = [&](int kk) {
#pragma unroll
        for (int s = 0; s < 4; s++) {
            pb[s * 2 + 0] = __ldg(wT + wro + kk * 32 + s * 8);
            pb[s * 2 + 1] = __ldg(wT + wro + kk * 32 + s * 8 + 4);
        }
    };
    auto stsAB = [&](int buf) {
        float* base = smem + 128 + buf * BUF_FLOATS;
        if (wid < 8) {
#pragma unroll
            for (int s = 0; s < 4; s++)
                stsA_s(base, base + 4096, ((s * 8 + wid) * 32 + lane) * 4, pa + s * 4);
        }
#pragma unroll
        for (int s = 0; s < 4; s++)
            stsB_s(base + 8192, base + 12288, ((s * 16 + wid) * 32 + lane) * 2,
                   pb[s * 2 + 0], pb[s * 2 + 1]);
    };

    float acc[2][4][4];
#pragma unroll
    for (int i = 0; i < 2; i++)
#pragma unroll
        for (int j = 0; j < 4; j++)
#pragma unroll
            for (int e = 0; e < 4; e++) acc[i][j][e] = 0.f;

    if (wid < 8) loadA(0);
    loadB(0);
    stsAB(0);
    __syncthreads();

    for (int kk = 0; kk < NCH; kk++) {
        if (kk + 1 < NCH) { if (wid < 8) loadA(kk + 1); loadB(kk + 1); }
        compute_chunk(smem + 128 + (kk & 1) * BUF_FLOATS, wm, wn, lane, acc);
        if (kk + 1 < NCH) stsAB((kk + 1) & 1);
        __syncthreads();
    }

    // epilogue: bias + relu, NHWC store
#pragma unroll
    for (int i = 0; i < 2; i++) {
        int rlo = rowBase + (wm * 2 + i) * 16 + (lane >> 2);
        int rhi = rlo + 8;
#pragma unroll
        for (int j = 0; j < 4; j++) {
            int c = (wn * 4 + j) * 8 + 2 * (lane & 3);
            float b0 = aux[c], b1 = aux[c + 1];
            float2 v0 = make_float2(fmaxf(acc[i][j][0] + b0, 0.f), fmaxf(acc[i][j][1] + b1, 0.f));
            float2 v1 = make_float2(fmaxf(acc[i][j][2] + b0, 0.f), fmaxf(acc[i][j][3] + b1, 0.f));
            *reinterpret_cast<float2*>(out + (size_t)rlo * CO + co0 + c) = v0;
            *reinterpret_cast<float2*>(out + (size_t)rhi * CO + co0 + c) = v1;
        }
    }
}

// ===========================================================================
// Tensor-core VQ: S = zf(8192x256) @ cb^T; d = ||c||^2 - 2S; row argmin.
// ===========================================================================
__global__ __launch_bounds__(512) void vq_mma(const float* __restrict__ zf,
                                              const float* __restrict__ cb) {
    constexpr int NCH = 8;   // K = 256
    extern __shared__ __align__(16) float smem[];
    float* aux = smem;
    __shared__ unsigned long long smin[128];

    int tid = threadIdx.x, lane = tid & 31, wid = tid >> 5;
    int wm = wid >> 2, wn = wid & 3;
    int colBase = blockIdx.x * 128;
    int rowBase = blockIdx.y * 128;

    if (tid < 128) { aux[tid] = g_cbnorm[colBase + tid]; smin[tid] = ~0ULL; }

    const float* pA0 = zf + (size_t)(rowBase + wid * 16 + (lane >> 2)) * 256 + (lane & 3);
    const float* pA1 = pA0 + 8 * 256;
    const float* pB = cb + (size_t)(colBase + wid * 8 + (lane >> 2)) * 256 + (lane & 3);

    float pa[16], pb[8];
    auto loadAB = [&](int kk) {
        if (wid < 8) {
#pragma unroll
            for (int s = 0; s < 4; s++) {
                pa[s * 4 + 0] = __ldg(pA0 + kk * 32 + s * 8);
                pa[s * 4 + 1] = __ldg(pA1 + kk * 32 + s * 8);
                pa[s * 4 + 2] = __ldg(pA0 + kk * 32 + s * 8 + 4);
                pa[s * 4 + 3] = __ldg(pA1 + kk * 32 + s * 8 + 4);
            }
        }
#pragma unroll
        for (int s = 0; s < 4; s++) {
            pb[s * 2 + 0] = __ldg(pB + kk * 32 + s * 8);
            pb[s * 2 + 1] = __ldg(pB + kk * 32 + s * 8 + 4);
        }
    };
    auto stsAB = [&](int buf) {
        float* base = smem + 128 + buf * BUF_FLOATS;
        if (wid < 8) {
#pragma unroll
            for (int s = 0; s < 4; s++)
                stsA_s(base, base + 4096, ((s * 8 + wid) * 32 + lane) * 4, pa + s * 4);
        }
#pragma unroll
        for (int s = 0; s < 4; s++)
            stsB_s(base + 8192, base + 12288, ((s * 16 + wid) * 32 + lane) * 2,
                   pb[s * 2 + 0], pb[s * 2 + 1]);
    };

    float acc[2][4][4];
#pragma unroll
    for (int i = 0; i < 2; i++)
#pragma unroll
        for (int j = 0; j < 4; j++)
#pragma unroll
            for (int e = 0; e < 4; e++) acc[i][j][e] = 0.f;

    loadAB(0);
    stsAB(0);
    __syncthreads();

    for (int kk = 0; kk < NCH; kk++) {
        if (kk + 1 < NCH) loadAB(kk + 1);
        compute_chunk(smem + 128 + (kk & 1) * BUF_FLOATS, wm, wn, lane, acc);
        if (kk + 1 < NCH) stsAB((kk + 1) & 1);
        __syncthreads();
    }

    // argmin epilogue
#pragma unroll
    for (int i = 0; i < 2; i++) {
        int rlo = (wm * 2 + i) * 16 + (lane >> 2);
        float bestl = __int_as_float(0x7f800000); int bcl = 0;
        float besth = __int_as_float(0x7f800000); int bch = 0;
#pragma unroll
        for (int j = 0; j < 4; j++) {
            int c = (wn * 4 + j) * 8 + 2 * (lane & 3);
            float n0 = aux[c], n1 = aux[c + 1];
            float d0 = n0 - 2.f * acc[i][j][0];
            float d1 = n1 - 2.f * acc[i][j][1];
            float d2 = n0 - 2.f * acc[i][j][2];
            float d3 = n1 - 2.f * acc[i][j][3];
            if (d0 < bestl) { bestl = d0; bcl = c; }
            if (d1 < bestl) { bestl = d1; bcl = c + 1; }
            if (d2 < besth) { besth = d2; bch = c; }
            if (d3 < besth) { besth = d3; bch = c + 1; }
        }
        unsigned ul = __float_as_uint(bestl);
        ul ^= (ul & 0x80000000u) ? 0xFFFFFFFFu : 0x80000000u;
        unsigned uh = __float_as_uint(besth);
        uh ^= (uh & 0x80000000u) ? 0xFFFFFFFFu : 0x80000000u;
        atomicMin(&smin[rlo], ((unsigned long long)ul << 32) | (unsigned)(colBase + bcl));
        atomicMin(&smin[rlo + 8], ((unsigned long long)uh << 32) | (unsigned)(colBase + bch));
    }
    __syncthreads();
    if (tid < 128) atomicMin(&g_min[rowBase + tid], smin[tid]);
}

// ===========================================================================
// cbnorm (warp per code row, fused g_min init) / gather
// ===========================================================================
__global__ void cbnorm_kernel(const float* __restrict__ cb) {
    int w = (blockIdx.x * 256 + threadIdx.x) >> 5;   // 8192 warps
    int lane = threadIdx.x & 31;
    const float4* p = reinterpret_cast<const float4*>(cb + (size_t)w * 256);
    float4 v0 = __ldg(p + lane);
    float4 v1 = __ldg(p + lane + 32);
    float s = v0.x * v0.x + v0.y * v0.y + v0.z * v0.z + v0.w * v0.w
            + v1.x * v1.x + v1.y * v1.y + v1.z * v1.z + v1.w * v1.w;
#pragma unroll
    for (int o = 16; o > 0; o >>= 1) s += __shfl_xor_sync(0xFFFFFFFFu, s, o);
    if (lane == 0) { g_cbnorm[w] = s; g_min[w] = ~0ULL; }
}

__global__ void gather_kernel(const float* __restrict__ cb,
                              float* __restrict__ out,
                              int write_zq, int write_idx, long idx_off) {
    int row = blockIdx.x;
    int c = threadIdx.x;
    unsigned idx = (unsigned)(g_min[row] & 0xFFFFFFFFu);
    if (write_zq) {
        float v = __ldg(cb + (size_t)idx * 256 + c);
        int n = row >> 8;
        int p = row & 255;
        out[(size_t)n * 65536 + (size_t)c * 256 + p] = v;
    }
    if (write_idx && c == 0) out[idx_off + row] = (float)idx;
}

// ===========================================================================
// Launch
// ===========================================================================
extern "C" void kernel_launch(void* const* d_in, const int* in_sizes, int n_in,
                              void* d_out, int out_size) {
    const float* x  = (const float*)d_in[0];
    const float* w1 = (const float*)d_in[1];
    const float* b1 = (const float*)d_in[2];
    const float* w2 = (const float*)d_in[3];
    const float* b2 = (const float*)d_in[4];
    const float* w3 = (const float*)d_in[5];
    const float* b3 = (const float*)d_in[6];
    const float* w4 = (const float*)d_in[7];
    const float* b4 = (const float*)d_in[8];
    const float* cb = (const float*)d_in[9];
    float* out = (float*)d_out;

    float* a1;  cudaGetSymbolAddress((void**)&a1,  g_a1);
    float* a2;  cudaGetSymbolAddress((void**)&a2,  g_a2);
    float* a3;  cudaGetSymbolAddress((void**)&a3,  g_a3);
    float* zf;  cudaGetSymbolAddress((void**)&zf,  g_zf);
    float* wt2; cudaGetSymbolAddress((void**)&wt2, g_wt2);
    float* wt3; cudaGetSymbolAddress((void**)&wt3, g_wt3);
    float* wt4; cudaGetSymbolAddress((void**)&wt4, g_wt4);

    static int attr_done = 0;
    if (!attr_done) {
        cudaFuncSetAttribute(conv_mma<64, 128, 128, 128>, cudaFuncAttributeMaxDynamicSharedMemorySize, GEMM_SMEM);
        cudaFuncSetAttribute(conv_mma<128, 256, 64, 64>, cudaFuncAttributeMaxDynamicSharedMemorySize, GEMM_SMEM);
        cudaFuncSetAttribute(conv_mma<256, 256, 32, 32>, cudaFuncAttributeMaxDynamicSharedMemorySize, GEMM_SMEM);
        cudaFuncSetAttribute(vq_mma, cudaFuncAttributeMaxDynamicSharedMemorySize, GEMM_SMEM);
        attr_done = 1;
    }

    // weight transposes + codebook norms (tiny)
    wtrans_kernel<<<(128 * 1024 + 255) / 256, 256>>>(w2, wt2, 64, 128);
    wtrans_kernel<<<(256 * 2048 + 255) / 256, 256>>>(w3, wt3, 128, 256);
    wtrans_kernel<<<(256 * 4096 + 255) / 256, 256>>>(w4, wt4, 256, 256);
    cbnorm_kernel<<<1024, 256>>>(cb);

    // conv chain (NHWC)
    conv1_nhwc<<<4096, 256>>>(x, w1, b1, a1);
    conv_mma<64, 128, 128, 128><<<dim3(1024, 1), 512, GEMM_SMEM>>>(a1, wt2, b2, a2);
    conv_mma<128, 256, 64, 64><<<dim3(256, 2), 512, GEMM_SMEM>>>(a2, wt3, b3, a3);
    conv_mma<256, 256, 32, 32><<<dim3(64, 2), 512, GEMM_SMEM>>>(a3, wt4, b4, zf);

    // VQ
    vq_mma<<<dim3(64, 64), 512, GEMM_SMEM>>>(zf, cb);

    // output: [z_q (2,097,152 floats)] [idx (8,192, cast to float)]
    const long ZQ = 2097152;
    int write_zq = 0, write_idx = 0; long idx_off = 0;
    if (out_size >= (int)(ZQ + 8192)) { write_zq = 1; write_idx = 1; idx_off = ZQ; }
    else if (out_size >= (int)ZQ)     { write_zq = 1; }
    else                              { write_idx = 1; idx_off = 0; }

    gather_kernel<<<8192, 256>>>(cb, out, write_zq, write_idx, idx_off);
}

// round 9
// speedup vs baseline: 1.0903x; 1.0903x over previous
#include <cuda_runtime.h>
#include <cstdint>

// ===========================================================================
// Scratch (__device__ globals; no allocation allowed)
// ===========================================================================
__device__ float g_a1[32u * 128u * 128u * 64u];   // conv1 out NHWC
__device__ float g_a2[32u * 64u * 64u * 128u];    // conv2 out NHWC
__device__ float g_a3[32u * 32u * 32u * 256u];    // conv3 out NHWC
__device__ float g_zf[8192u * 256u];              // conv4 out NHWC == zf
__device__ float g_wt2[128u * 1024u];             // w2 as [co][tap*CI+ci]
__device__ float g_wt3[256u * 2048u];
__device__ float g_wt4[256u * 4096u];
__device__ float g_cbnorm[8192];
__device__ unsigned long long g_min[8192];

// ===========================================================================
// mma.sync tf32 helpers (sm_80+ features; valid on plain sm_100 target)
// ===========================================================================
__device__ __forceinline__ void split1(float v, uint32_t& h, uint32_t& l) {
    uint32_t hu;
    asm("cvt.rna.tf32.f32 %0, %1;" : "=r"(hu) : "f"(v));
    float lf = v - __uint_as_float(hu);
    uint32_t lu;
    asm("cvt.rna.tf32.f32 %0, %1;" : "=r"(lu) : "f"(lf));
    h = hu; l = lu;
}

__device__ __forceinline__ void mma8(float* d, const uint32_t* a, const uint32_t* b) {
    asm volatile(
        "mma.sync.aligned.m16n8k8.row.col.f32.tf32.tf32.f32 "
        "{%0,%1,%2,%3}, {%4,%5,%6,%7}, {%8,%9}, {%0,%1,%2,%3};"
        : "+f"(d[0]), "+f"(d[1]), "+f"(d[2]), "+f"(d[3])
        : "r"(a[0]), "r"(a[1]), "r"(a[2]), "r"(a[3]), "r"(b[0]), "r"(b[1]));
}

// SMEM buffer layout (floats): per buffer AH[4096] AL[4096] BH[4096] BL[4096].
// A plane index: ((s*8 + mblk)*32 + lane)*4 + slot   (4 x 8 x 32 x 4)
// B plane index: ((s*16 + nblk)*32 + lane)*2 + slot  (4 x 16 x 32 x 2)
static constexpr int BUF_FLOATS = 16384;
static constexpr int GEMM_SMEM = (128 + 2 * BUF_FLOATS) * 4;   // 131584 bytes

// Compute one K=32 chunk from hi/lo planes. Warp tile 64x32 (4 m-blocks, 4 n-blocks).
// 8 warps arranged 2 (m) x 4 (n).
__device__ __forceinline__ void compute_chunk(const float* buf, int wm, int wn, int lane,
                                              float acc[4][4][4]) {
    const float* AH = buf;
    const float* AL = buf + 4096;
    const float* BH = buf + 8192;
    const float* BL = buf + 12288;
#pragma unroll
    for (int s = 0; s < 4; s++) {
        uint4 ah[4], al[4];
        uint2 bh[4], bl[4];
#pragma unroll
        for (int i = 0; i < 4; i++) {
            int idx = ((s * 8 + wm * 4 + i) * 32 + lane) * 4;
            ah[i] = *reinterpret_cast<const uint4*>(AH + idx);
            al[i] = *reinterpret_cast<const uint4*>(AL + idx);
        }
#pragma unroll
        for (int j = 0; j < 4; j++) {
            int idx = ((s * 16 + wn * 4 + j) * 32 + lane) * 2;
            bh[j] = *reinterpret_cast<const uint2*>(BH + idx);
            bl[j] = *reinterpret_cast<const uint2*>(BL + idx);
        }
#pragma unroll
        for (int i = 0; i < 4; i++)
#pragma unroll
            for (int j = 0; j < 4; j++) {
                mma8(acc[i][j], &ah[i].x, &bh[j].x);
                mma8(acc[i][j], &al[i].x, &bh[j].x);
                mma8(acc[i][j], &ah[i].x, &bl[j].x);
            }
    }
}

// Split 4 A values and store into hi/lo planes (one float4 each).
__device__ __forceinline__ void stsA_s(float* AH, float* AL, int idx, const float* pa4) {
    uint4 h, l;
    split1(pa4[0], h.x, l.x);
    split1(pa4[1], h.y, l.y);
    split1(pa4[2], h.z, l.z);
    split1(pa4[3], h.w, l.w);
    *reinterpret_cast<uint4*>(AH + idx) = h;
    *reinterpret_cast<uint4*>(AL + idx) = l;
}
__device__ __forceinline__ void stsB_s(float* BH, float* BL, int idx, float v0, float v1) {
    uint2 h, l;
    split1(v0, h.x, l.x);
    split1(v1, h.y, l.y);
    *reinterpret_cast<uint2*>(BH + idx) = h;
    *reinterpret_cast<uint2*>(BL + idx) = l;
}

// ===========================================================================
// Weight transpose: w[co][ci][kh][kw] -> wT[co][ (kh*4+kw)*CI + ci ]
// ===========================================================================
__global__ void wtrans_kernel(const float* __restrict__ w, float* __restrict__ wT,
                              int CI, int CO) {
    int id = blockIdx.x * 256 + threadIdx.x;
    int K = CI * 16;
    if (id >= CO * K) return;
    int co = id / K;
    int r = id % K;
    int tap = r / CI;
    int ci = r % CI;
    wT[id] = w[(co * CI + ci) * 16 + tap];
}

// ===========================================================================
// Conv1: CI=3, k=4 s=2 p=1 + bias + ReLU. NCHW in -> NHWC out.
// ===========================================================================
__global__ __launch_bounds__(256) void conv1_nhwc(const float* __restrict__ x,
                                                  const float* __restrict__ w,
                                                  const float* __restrict__ b,
                                                  float* __restrict__ out) {
    __shared__ __align__(16) float ws[48][64];
    __shared__ float sb[64];
    int tid = threadIdx.x;
    for (int i = tid; i < 3072; i += 256) {
        int tap = i >> 6, co = i & 63;
        ws[tap][co] = w[co * 48 + tap];
    }
    if (tid < 64) sb[tid] = b[tid];
    __syncthreads();

    int p = blockIdx.x * 128 + (tid >> 1);
    int half = tid & 1;
    int n = p >> 14;
    int rp = p & 16383;
    int ho = rp >> 7, wo = rp & 127;
    int hb = 2 * ho - 1, wb = 2 * wo - 1;
    const float* xb = x + (size_t)n * 3 * 65536;

    float acc[32];
#pragma unroll
    for (int c = 0; c < 32; c++) acc[c] = sb[half * 32 + c];

    for (int ci = 0; ci < 3; ci++) {
        const float* xc = xb + ci * 65536;
        for (int kh = 0; kh < 4; kh++) {
            int hi = hb + kh;
            if ((unsigned)hi >= 256u) continue;
            const float* xr = xc + hi * 256;
            for (int kw = 0; kw < 4; kw++) {
                int wi = wb + kw;
                if ((unsigned)wi >= 256u) continue;
                float v = __ldg(xr + wi);
                const float4* wr = reinterpret_cast<const float4*>(&ws[ci * 16 + kh * 4 + kw][half * 32]);
#pragma unroll
                for (int c4 = 0; c4 < 8; c4++) {
                    float4 wv = wr[c4];
                    acc[c4 * 4 + 0] = fmaf(v, wv.x, acc[c4 * 4 + 0]);
                    acc[c4 * 4 + 1] = fmaf(v, wv.y, acc[c4 * 4 + 1]);
                    acc[c4 * 4 + 2] = fmaf(v, wv.z, acc[c4 * 4 + 2]);
                    acc[c4 * 4 + 3] = fmaf(v, wv.w, acc[c4 * 4 + 3]);
                }
            }
        }
    }
    float* op = out + (size_t)p * 64 + half * 32;
#pragma unroll
    for (int c4 = 0; c4 < 8; c4++) {
        float4 v;
        v.x = fmaxf(acc[c4 * 4 + 0], 0.f);
        v.y = fmaxf(acc[c4 * 4 + 1], 0.f);
        v.z = fmaxf(acc[c4 * 4 + 2], 0.f);
        v.w = fmaxf(acc[c4 * 4 + 3], 0.f);
        reinterpret_cast<float4*>(op)[c4] = v;
    }
}

// ===========================================================================
// Tensor-core implicit-GEMM conv (k=4 s=2 p=1) + bias + ReLU, NHWC->NHWC.
// Block 128x128, K = CI*16 chunked by 32; 256 threads, 8 warps, warp 64x32.
// 3xTF32 via mma.sync; hi/lo split done once at fill into smem planes.
// ===========================================================================
template <int CI, int CO, int HI, int WI>
__global__ __launch_bounds__(256) void conv_mma(const float* __restrict__ in,
                                                const float* __restrict__ wT,
                                                const float* __restrict__ bias,
                                                float* __restrict__ out) {
    constexpr int HO = HI / 2, WO = WI / 2;
    constexpr int K = CI * 16;
    constexpr int NCH = K / 32;
    extern __shared__ __align__(16) float smem[];
    float* aux = smem;

    int tid = threadIdx.x, lane = tid & 31, wid = tid >> 5;
    int wm = wid >> 2, wn = wid & 3;
    int rowBase = blockIdx.x * 128;
    int co0 = blockIdx.y * 128;

    if (tid < 128) aux[tid] = bias[co0 + tid];

    // --- A fill: warp wid = m-block (0..7); 2 pixel rows per thread ---
    int rA0 = rowBase + wid * 16 + (lane >> 2);
    int rA1 = rA0 + 8;
    int n0 = rA0 / (HO * WO), rp0 = rA0 % (HO * WO);
    int n1 = rA1 / (HO * WO), rp1 = rA1 % (HO * WO);
    int hb0 = 2 * (rp0 / WO) - 1, wb0 = 2 * (rp0 % WO) - 1;
    int hb1 = 2 * (rp1 / WO) - 1, wb1 = 2 * (rp1 % WO) - 1;
    size_t ab0 = (size_t)n0 * HI * WI * CI;
    size_t ab1 = (size_t)n1 * HI * WI * CI;

    // --- B fill: warp wid covers n-blocks wid and wid+8; 2 weight rows/thread ---
    size_t wro0 = (size_t)(co0 + wid * 8 + (lane >> 2)) * K + (lane & 3);
    size_t wro1 = (size_t)(co0 + (wid + 8) * 8 + (lane >> 2)) * K + (lane & 3);

    float pa[16], pb[16];
    auto loadA = [&](int kk) {
        int kk32 = kk * 32;
        int tap = kk32 / CI, ci0 = kk32 % CI;
        int kh = tap >> 2, kw = tap & 3;
        int hi0 = hb0 + kh, wi0 = wb0 + kw;
        int hi1 = hb1 + kh, wi1 = wb1 + kw;
        bool ok0 = (unsigned)hi0 < (unsigned)HI && (unsigned)wi0 < (unsigned)WI;
        bool ok1 = (unsigned)hi1 < (unsigned)HI && (unsigned)wi1 < (unsigned)WI;
        const float* p0 = in + ab0 + ((size_t)hi0 * WI + wi0) * CI + ci0 + (lane & 3);
        const float* p1 = in + ab1 + ((size_t)hi1 * WI + wi1) * CI + ci0 + (lane & 3);
#pragma unroll
        for (int s = 0; s < 4; s++) {
            pa[s * 4 + 0] = ok0 ? __ldg(p0 + s * 8) : 0.f;
            pa[s * 4 + 1] = ok1 ? __ldg(p1 + s * 8) : 0.f;
            pa[s * 4 + 2] = ok0 ? __ldg(p0 + s * 8 + 4) : 0.f;
            pa[s * 4 + 3] = ok1 ? __ldg(p1 + s * 8 + 4) : 0.f;
        }
    };
    auto loadB = [&](int kk) {
#pragma unroll
        for (int s = 0; s < 4; s++) {
            pb[s * 2 + 0] = __ldg(wT + wro0 + kk * 32 + s * 8);
            pb[s * 2 + 1] = __ldg(wT + wro0 + kk * 32 + s * 8 + 4);
            pb[8 + s * 2 + 0] = __ldg(wT + wro1 + kk * 32 + s * 8);
            pb[8 + s * 2 + 1] = __ldg(wT + wro1 + kk * 32 + s * 8 + 4);
        }
    };
    auto stsAB = [&](int buf) {
        float* base = smem + 128 + buf * BUF_FLOATS;
#pragma unroll
        for (int s = 0; s < 4; s++)
            stsA_s(base, base + 4096, ((s * 8 + wid) * 32 + lane) * 4, pa + s * 4);
#pragma unroll
        for (int s = 0; s < 4; s++) {
            stsB_s(base + 8192, base + 12288, ((s * 16 + wid) * 32 + lane) * 2,
                   pb[s * 2 + 0], pb[s * 2 + 1]);
            stsB_s(base + 8192, base + 12288, ((s * 16 + wid + 8) * 32 + lane) * 2,
                   pb[8 + s * 2 + 0], pb[8 + s * 2 + 1]);
        }
    };

    float acc[4][4][4];
#pragma unroll
    for (int i = 0; i < 4; i++)
#pragma unroll
        for (int j = 0; j < 4; j++)
#pragma unroll
            for (int e = 0; e < 4; e++) acc[i][j][e] = 0.f;

    loadA(0); loadB(0);
    stsAB(0);
    __syncthreads();

    for (int kk = 0; kk < NCH; kk++) {
        if (kk + 1 < NCH) { loadA(kk + 1); loadB(kk + 1); }
        compute_chunk(smem + 128 + (kk & 1) * BUF_FLOATS, wm, wn, lane, acc);
        if (kk + 1 < NCH) stsAB((kk + 1) & 1);
        __syncthreads();
    }

    // epilogue: bias + relu, NHWC store
#pragma unroll
    for (int i = 0; i < 4; i++) {
        int rlo = rowBase + (wm * 4 + i) * 16 + (lane >> 2);
        int rhi = rlo + 8;
#pragma unroll
        for (int j = 0; j < 4; j++) {
            int c = (wn * 4 + j) * 8 + 2 * (lane & 3);
            float b0 = aux[c], b1 = aux[c + 1];
            float2 v0 = make_float2(fmaxf(acc[i][j][0] + b0, 0.f), fmaxf(acc[i][j][1] + b1, 0.f));
            float2 v1 = make_float2(fmaxf(acc[i][j][2] + b0, 0.f), fmaxf(acc[i][j][3] + b1, 0.f));
            *reinterpret_cast<float2*>(out + (size_t)rlo * CO + co0 + c) = v0;
            *reinterpret_cast<float2*>(out + (size_t)rhi * CO + co0 + c) = v1;
        }
    }
}

// ===========================================================================
// Tensor-core VQ: S = zf(8192x256) @ cb^T; d = ||c||^2 - 2S; row argmin.
// ===========================================================================
__global__ __launch_bounds__(256) void vq_mma(const float* __restrict__ zf,
                                              const float* __restrict__ cb) {
    constexpr int NCH = 8;   // K = 256
    extern __shared__ __align__(16) float smem[];
    float* aux = smem;
    __shared__ unsigned long long smin[128];

    int tid = threadIdx.x, lane = tid & 31, wid = tid >> 5;
    int wm = wid >> 2, wn = wid & 3;
    int colBase = blockIdx.x * 128;
    int rowBase = blockIdx.y * 128;

    if (tid < 128) { aux[tid] = g_cbnorm[colBase + tid]; smin[tid] = ~0ULL; }

    const float* pA0 = zf + (size_t)(rowBase + wid * 16 + (lane >> 2)) * 256 + (lane & 3);
    const float* pA1 = pA0 + 8 * 256;
    const float* pB0 = cb + (size_t)(colBase + wid * 8 + (lane >> 2)) * 256 + (lane & 3);
    const float* pB1 = cb + (size_t)(colBase + (wid + 8) * 8 + (lane >> 2)) * 256 + (lane & 3);

    float pa[16], pb[16];
    auto loadAB = [&](int kk) {
#pragma unroll
        for (int s = 0; s < 4; s++) {
            pa[s * 4 + 0] = __ldg(pA0 + kk * 32 + s * 8);
            pa[s * 4 + 1] = __ldg(pA1 + kk * 32 + s * 8);
            pa[s * 4 + 2] = __ldg(pA0 + kk * 32 + s * 8 + 4);
            pa[s * 4 + 3] = __ldg(pA1 + kk * 32 + s * 8 + 4);
            pb[s * 2 + 0] = __ldg(pB0 + kk * 32 + s * 8);
            pb[s * 2 + 1] = __ldg(pB0 + kk * 32 + s * 8 + 4);
            pb[8 + s * 2 + 0] = __ldg(pB1 + kk * 32 + s * 8);
            pb[8 + s * 2 + 1] = __ldg(pB1 + kk * 32 + s * 8 + 4);
        }
    };
    auto stsAB = [&](int buf) {
        float* base = smem + 128 + buf * BUF_FLOATS;
#pragma unroll
        for (int s = 0; s < 4; s++)
            stsA_s(base, base + 4096, ((s * 8 + wid) * 32 + lane) * 4, pa + s * 4);
#pragma unroll
        for (int s = 0; s < 4; s++) {
            stsB_s(base + 8192, base + 12288, ((s * 16 + wid) * 32 + lane) * 2,
                   pb[s * 2 + 0], pb[s * 2 + 1]);
            stsB_s(base + 8192, base + 12288, ((s * 16 + wid + 8) * 32 + lane) * 2,
                   pb[8 + s * 2 + 0], pb[8 + s * 2 + 1]);
        }
    };

    float acc[4][4][4];
#pragma unroll
    for (int i = 0; i < 4; i++)
#pragma unroll
        for (int j = 0; j < 4; j++)
#pragma unroll
            for (int e = 0; e < 4; e++) acc[i][j][e] = 0.f;

    loadAB(0);
    stsAB(0);
    __syncthreads();

    for (int kk = 0; kk < NCH; kk++) {
        if (kk + 1 < NCH) loadAB(kk + 1);
        compute_chunk(smem + 128 + (kk & 1) * BUF_FLOATS, wm, wn, lane, acc);
        if (kk + 1 < NCH) stsAB((kk + 1) & 1);
        __syncthreads();
    }

    // argmin epilogue
#pragma unroll
    for (int i = 0; i < 4; i++) {
        int rlo = (wm * 4 + i) * 16 + (lane >> 2);
        float bestl = __int_as_float(0x7f800000); int bcl = 0;
        float besth = __int_as_float(0x7f800000); int bch = 0;
#pragma unroll
        for (int j = 0; j < 4; j++) {
            int c = (wn * 4 + j) * 8 + 2 * (lane & 3);
            float n0 = aux[c], n1 = aux[c + 1];
            float d0 = n0 - 2.f * acc[i][j][0];
            float d1 = n1 - 2.f * acc[i][j][1];
            float d2 = n0 - 2.f * acc[i][j][2];
            float d3 = n1 - 2.f * acc[i][j][3];
            if (d0 < bestl) { bestl = d0; bcl = c; }
            if (d1 < bestl) { bestl = d1; bcl = c + 1; }
            if (d2 < besth) { besth = d2; bch = c; }
            if (d3 < besth) { besth = d3; bch = c + 1; }
        }
        unsigned ul = __float_as_uint(bestl);
        ul ^= (ul & 0x80000000u) ? 0xFFFFFFFFu : 0x80000000u;
        unsigned uh = __float_as_uint(besth);
        uh ^= (uh & 0x80000000u) ? 0xFFFFFFFFu : 0x80000000u;
        atomicMin(&smin[rlo], ((unsigned long long)ul << 32) | (unsigned)(colBase + bcl));
        atomicMin(&smin[rlo + 8], ((unsigned long long)uh << 32) | (unsigned)(colBase + bch));
    }
    __syncthreads();
    if (tid < 128) atomicMin(&g_min[rowBase + tid], smin[tid]);
}

// ===========================================================================
// cbnorm (warp per code row, fused g_min init) / gather
// ===========================================================================
__global__ void cbnorm_kernel(const float* __restrict__ cb) {
    int w = (blockIdx.x * 256 + threadIdx.x) >> 5;   // 8192 warps
    int lane = threadIdx.x & 31;
    const float4* p = reinterpret_cast<const float4*>(cb + (size_t)w * 256);
    float4 v0 = __ldg(p + lane);
    float4 v1 = __ldg(p + lane + 32);
    float s = v0.x * v0.x + v0.y * v0.y + v0.z * v0.z + v0.w * v0.w
            + v1.x * v1.x + v1.y * v1.y + v1.z * v1.z + v1.w * v1.w;
#pragma unroll
    for (int o = 16; o > 0; o >>= 1) s += __shfl_xor_sync(0xFFFFFFFFu, s, o);
    if (lane == 0) { g_cbnorm[w] = s; g_min[w] = ~0ULL; }
}

__global__ void gather_kernel(const float* __restrict__ cb,
                              float* __restrict__ out,
                              int write_zq, int write_idx, long idx_off) {
    int row = blockIdx.x;
    int c = threadIdx.x;
    unsigned idx = (unsigned)(g_min[row] & 0xFFFFFFFFu);
    if (write_zq) {
        float v = __ldg(cb + (size_t)idx * 256 + c);
        int n = row >> 8;
        int p = row & 255;
        out[(size_t)n * 65536 + (size_t)c * 256 + p] = v;
    }
    if (write_idx && c == 0) out[idx_off + row] = (float)idx;
}

// ===========================================================================
// Launch
// ===========================================================================
extern "C" void kernel_launch(void* const* d_in, const int* in_sizes, int n_in,
                              void* d_out, int out_size) {
    const float* x  = (const float*)d_in[0];
    const float* w1 = (const float*)d_in[1];
    const float* b1 = (const float*)d_in[2];
    const float* w2 = (const float*)d_in[3];
    const float* b2 = (const float*)d_in[4];
    const float* w3 = (const float*)d_in[5];
    const float* b3 = (const float*)d_in[6];
    const float* w4 = (const float*)d_in[7];
    const float* b4 = (const float*)d_in[8];
    const float* cb = (const float*)d_in[9];
    float* out = (float*)d_out;

    float* a1;  cudaGetSymbolAddress((void**)&a1,  g_a1);
    float* a2;  cudaGetSymbolAddress((void**)&a2,  g_a2);
    float* a3;  cudaGetSymbolAddress((void**)&a3,  g_a3);
    float* zf;  cudaGetSymbolAddress((void**)&zf,  g_zf);
    float* wt2; cudaGetSymbolAddress((void**)&wt2, g_wt2);
    float* wt3; cudaGetSymbolAddress((void**)&wt3, g_wt3);
    float* wt4; cudaGetSymbolAddress((void**)&wt4, g_wt4);

    static int attr_done = 0;
    if (!attr_done) {
        cudaFuncSetAttribute(conv_mma<64, 128, 128, 128>, cudaFuncAttributeMaxDynamicSharedMemorySize, GEMM_SMEM);
        cudaFuncSetAttribute(conv_mma<128, 256, 64, 64>, cudaFuncAttributeMaxDynamicSharedMemorySize, GEMM_SMEM);
        cudaFuncSetAttribute(conv_mma<256, 256, 32, 32>, cudaFuncAttributeMaxDynamicSharedMemorySize, GEMM_SMEM);
        cudaFuncSetAttribute(vq_mma, cudaFuncAttributeMaxDynamicSharedMemorySize, GEMM_SMEM);
        attr_done = 1;
    }

    // weight transposes + codebook norms (tiny)
    wtrans_kernel<<<(128 * 1024 + 255) / 256, 256>>>(w2, wt2, 64, 128);
    wtrans_kernel<<<(256 * 2048 + 255) / 256, 256>>>(w3, wt3, 128, 256);
    wtrans_kernel<<<(256 * 4096 + 255) / 256, 256>>>(w4, wt4, 256, 256);
    cbnorm_kernel<<<1024, 256>>>(cb);

    // conv chain (NHWC)
    conv1_nhwc<<<4096, 256>>>(x, w1, b1, a1);
    conv_mma<64, 128, 128, 128><<<dim3(1024, 1), 256, GEMM_SMEM>>>(a1, wt2, b2, a2);
    conv_mma<128, 256, 64, 64><<<dim3(256, 2), 256, GEMM_SMEM>>>(a2, wt3, b3, a3);
    conv_mma<256, 256, 32, 32><<<dim3(64, 2), 256, GEMM_SMEM>>>(a3, wt4, b4, zf);

    // VQ
    vq_mma<<<dim3(64, 64), 256, GEMM_SMEM>>>(zf, cb);

    // output: [z_q (2,097,152 floats)] [idx (8,192, cast to float)]
    const long ZQ = 2097152;
    int write_zq = 0, write_idx = 0; long idx_off = 0;
    if (out_size >= (int)(ZQ + 8192)) { write_zq = 1; write_idx = 1; idx_off = ZQ; }
    else if (out_size >= (int)ZQ)     { write_zq = 1; }
    else                              { write_idx = 1; idx_off = 0; }

    gather_kernel<<<8192, 256>>>(cb, out, write_zq, write_idx, idx_off);
}

// round 10
// speedup vs baseline: 1.6529x; 1.5161x over previous
#include <cuda_runtime.h>
#include <cuda_fp16.h>
#include <cstdint>

// ===========================================================================
// Scratch (__device__ globals; no allocation allowed)
// ===========================================================================
__device__ float g_a1[32u * 128u * 128u * 64u];   // conv1 out NHWC
__device__ float g_a2[32u * 64u * 64u * 128u];    // conv2 out NHWC
__device__ float g_a3[32u * 32u * 32u * 256u];    // conv3 out NHWC
__device__ float g_zf[8192u * 256u];              // conv4 out NHWC == zf
__device__ float g_wt2[128u * 1024u];             // w2 as [co][tap*CI+ci]
__device__ float g_wt3[256u * 2048u];
__device__ float g_wt4[256u * 4096u];
__device__ float g_cbnorm[8192];
__device__ unsigned long long g_min[8192];

// ===========================================================================
// fp16x2 "double-double" MMA helpers.
// Operands pre-scaled by 2^8:  a' = a*256 = a0 + a1 (both fp16, a1 normal).
// acc accumulates a'*b' = 65536 * (a*b) over 3 MMAs: a0b0 + a0b1 + a1b0.
// Epilogue multiplies by 1/65536. Dropped a1*b1 ~ 2^-22 (same as 3xTF32's lolo).
// ===========================================================================
__device__ __forceinline__ uint32_t packh2(__half x, __half y) {
    __half2 h = __halves2half2(x, y);
    return *reinterpret_cast<uint32_t*>(&h);
}
// split a float2 (two consecutive k values) into hi/lo fp16x2 words, scaled 2^8
__device__ __forceinline__ void split2(float2 v, uint32_t& hh, uint32_t& ll) {
    float sx = v.x * 256.f, sy = v.y * 256.f;
    __half hx = __float2half_rn(sx), hy = __float2half_rn(sy);
    float rx = sx - __half2float(hx), ry = sy - __half2float(hy);
    hh = packh2(hx, hy);
    ll = packh2(__float2half_rn(rx), __float2half_rn(ry));
}

__device__ __forceinline__ void mma16(float* d, const uint32_t* a, const uint32_t* b) {
    asm volatile(
        "mma.sync.aligned.m16n8k16.row.col.f32.f16.f16.f32 "
        "{%0,%1,%2,%3}, {%4,%5,%6,%7}, {%8,%9}, {%0,%1,%2,%3};"
        : "+f"(d[0]), "+f"(d[1]), "+f"(d[2]), "+f"(d[3])
        : "r"(a[0]), "r"(a[1]), "r"(a[2]), "r"(a[3]), "r"(b[0]), "r"(b[1]));
}

// SMEM buffer (u32 units): AH[2048] AL[2048] BH[2048] BL[2048] = 8192 u32 = 32KB.
// A plane index: ((s*8 + mblk)*32 + lane)*4 + reg   (s:2 k16-steps, mblk:8)
// B plane index: ((s*16 + nblk)*32 + lane)*2 + reg  (nblk:16)
static constexpr int BUF_U32 = 8192;
static constexpr int GEMM_SMEM = 128 * 4 + 2 * BUF_U32 * 4;   // 66048 bytes

// Compute one K=32 chunk. Warp tile 64x32 (4 m-blocks x 4 n-blocks), 8 warps 2x4.
__device__ __forceinline__ void compute_chunk(const uint32_t* buf, int wm, int wn, int lane,
                                              float acc[4][4][4]) {
    const uint32_t* AH = buf;
    const uint32_t* AL = buf + 2048;
    const uint32_t* BH = buf + 4096;
    const uint32_t* BL = buf + 6144;
#pragma unroll
    for (int s = 0; s < 2; s++) {
        uint4 ah[4], al[4];
        uint2 bh[4], bl[4];
#pragma unroll
        for (int i = 0; i < 4; i++) {
            int idx = ((s * 8 + wm * 4 + i) * 32 + lane) * 4;
            ah[i] = *reinterpret_cast<const uint4*>(AH + idx);
            al[i] = *reinterpret_cast<const uint4*>(AL + idx);
        }
#pragma unroll
        for (int j = 0; j < 4; j++) {
            int idx = ((s * 16 + wn * 4 + j) * 32 + lane) * 2;
            bh[j] = *reinterpret_cast<const uint2*>(BH + idx);
            bl[j] = *reinterpret_cast<const uint2*>(BL + idx);
        }
#pragma unroll
        for (int i = 0; i < 4; i++)
#pragma unroll
            for (int j = 0; j < 4; j++) {
                mma16(acc[i][j], &ah[i].x, &bh[j].x);
                mma16(acc[i][j], &al[i].x, &bh[j].x);
                mma16(acc[i][j], &ah[i].x, &bl[j].x);
            }
    }
}

// ===========================================================================
// Weight transpose: w[co][ci][kh][kw] -> wT[co][ (kh*4+kw)*CI + ci ]
// ===========================================================================
__global__ void wtrans_kernel(const float* __restrict__ w, float* __restrict__ wT,
                              int CI, int CO) {
    int id = blockIdx.x * 256 + threadIdx.x;
    int K = CI * 16;
    if (id >= CO * K) return;
    int co = id / K;
    int r = id % K;
    int tap = r / CI;
    int ci = r % CI;
    wT[id] = w[(co * CI + ci) * 16 + tap];
}

// ===========================================================================
// Conv1: CI=3, k=4 s=2 p=1 + bias + ReLU. NCHW in -> NHWC out.
// ===========================================================================
__global__ __launch_bounds__(256) void conv1_nhwc(const float* __restrict__ x,
                                                  const float* __restrict__ w,
                                                  const float* __restrict__ b,
                                                  float* __restrict__ out) {
    __shared__ __align__(16) float ws[48][64];
    __shared__ float sb[64];
    int tid = threadIdx.x;
    for (int i = tid; i < 3072; i += 256) {
        int tap = i >> 6, co = i & 63;
        ws[tap][co] = w[co * 48 + tap];
    }
    if (tid < 64) sb[tid] = b[tid];
    __syncthreads();

    int p = blockIdx.x * 128 + (tid >> 1);
    int half = tid & 1;
    int n = p >> 14;
    int rp = p & 16383;
    int ho = rp >> 7, wo = rp & 127;
    int hb = 2 * ho - 1, wb = 2 * wo - 1;
    const float* xb = x + (size_t)n * 3 * 65536;

    float acc[32];
#pragma unroll
    for (int c = 0; c < 32; c++) acc[c] = sb[half * 32 + c];

    for (int ci = 0; ci < 3; ci++) {
        const float* xc = xb + ci * 65536;
        for (int kh = 0; kh < 4; kh++) {
            int hi = hb + kh;
            if ((unsigned)hi >= 256u) continue;
            const float* xr = xc + hi * 256;
            for (int kw = 0; kw < 4; kw++) {
                int wi = wb + kw;
                if ((unsigned)wi >= 256u) continue;
                float v = __ldg(xr + wi);
                const float4* wr = reinterpret_cast<const float4*>(&ws[ci * 16 + kh * 4 + kw][half * 32]);
#pragma unroll
                for (int c4 = 0; c4 < 8; c4++) {
                    float4 wv = wr[c4];
                    acc[c4 * 4 + 0] = fmaf(v, wv.x, acc[c4 * 4 + 0]);
                    acc[c4 * 4 + 1] = fmaf(v, wv.y, acc[c4 * 4 + 1]);
                    acc[c4 * 4 + 2] = fmaf(v, wv.z, acc[c4 * 4 + 2]);
                    acc[c4 * 4 + 3] = fmaf(v, wv.w, acc[c4 * 4 + 3]);
                }
            }
        }
    }
    float* op = out + (size_t)p * 64 + half * 32;
#pragma unroll
    for (int c4 = 0; c4 < 8; c4++) {
        float4 v;
        v.x = fmaxf(acc[c4 * 4 + 0], 0.f);
        v.y = fmaxf(acc[c4 * 4 + 1], 0.f);
        v.z = fmaxf(acc[c4 * 4 + 2], 0.f);
        v.w = fmaxf(acc[c4 * 4 + 3], 0.f);
        reinterpret_cast<float4*>(op)[c4] = v;
    }
}

// ===========================================================================
// Shared fill helpers.
// pa0/pa1: row g / row g+8 float2 for [s:2][p:2]; stored as [s*2+p].
// ===========================================================================
__device__ __forceinline__ void stsA_fp16(uint32_t* base, int wid, int lane,
                                          const float2* pa0, const float2* pa1) {
    uint32_t* AH = base;
    uint32_t* AL = base + 2048;
#pragma unroll
    for (int s = 0; s < 2; s++) {
        uint4 h, l;
        split2(pa0[s * 2 + 0], h.x, l.x);   // reg0: row g,   k 2t..2t+1
        split2(pa1[s * 2 + 0], h.y, l.y);   // reg1: row g+8
        split2(pa0[s * 2 + 1], h.z, l.z);   // reg2: row g,   k 2t+8..2t+9
        split2(pa1[s * 2 + 1], h.w, l.w);   // reg3: row g+8
        int idx = ((s * 8 + wid) * 32 + lane) * 4;
        *reinterpret_cast<uint4*>(AH + idx) = h;
        *reinterpret_cast<uint4*>(AL + idx) = l;
    }
}
__device__ __forceinline__ void stsB_fp16(uint32_t* base, int nblk, int lane,
                                          const float2* pb) {   // pb[s*2+p]
    uint32_t* BH = base + 4096;
    uint32_t* BL = base + 6144;
#pragma unroll
    for (int s = 0; s < 2; s++) {
        uint2 h, l;
        split2(pb[s * 2 + 0], h.x, l.x);    // reg0: k 2t..2t+1
        split2(pb[s * 2 + 1], h.y, l.y);    // reg1: k 2t+8..2t+9
        int idx = ((s * 16 + nblk) * 32 + lane) * 2;
        *reinterpret_cast<uint2*>(BH + idx) = h;
        *reinterpret_cast<uint2*>(BL + idx) = l;
    }
}

// ===========================================================================
// Tensor-core implicit-GEMM conv (k=4 s=2 p=1) + bias + ReLU, NHWC->NHWC.
// Block 128x128, K = CI*16 chunked by 32; 256 threads, 8 warps, warp 64x32.
// fp16x2 double-double via m16n8k16 mma.sync (3 MMAs per k16).
// ===========================================================================
template <int CI, int CO, int HI, int WI>
__global__ __launch_bounds__(256) void conv_mma(const float* __restrict__ in,
                                                const float* __restrict__ wT,
                                                const float* __restrict__ bias,
                                                float* __restrict__ out) {
    constexpr int HO = HI / 2, WO = WI / 2;
    constexpr int K = CI * 16;
    constexpr int NCH = K / 32;
    extern __shared__ __align__(16) float smem[];
    float* aux = smem;
    uint32_t* bufs = reinterpret_cast<uint32_t*>(smem + 128);

    int tid = threadIdx.x, lane = tid & 31, wid = tid >> 5;
    int wm = wid >> 2, wn = wid & 3;
    int g = lane >> 2, t = lane & 3;
    int rowBase = blockIdx.x * 128;
    int co0 = blockIdx.y * 128;

    if (tid < 128) aux[tid] = bias[co0 + tid];

    // --- A fill: warp wid = m-block; rows g and g+8 of the block ---
    int rA0 = rowBase + wid * 16 + g;
    int rA1 = rA0 + 8;
    int n0 = rA0 / (HO * WO), rp0 = rA0 % (HO * WO);
    int n1 = rA1 / (HO * WO), rp1 = rA1 % (HO * WO);
    int hb0 = 2 * (rp0 / WO) - 1, wb0 = 2 * (rp0 % WO) - 1;
    int hb1 = 2 * (rp1 / WO) - 1, wb1 = 2 * (rp1 % WO) - 1;
    size_t ab0 = (size_t)n0 * HI * WI * CI;
    size_t ab1 = (size_t)n1 * HI * WI * CI;

    // --- B fill: warp wid covers n-blocks wid and wid+8; col = nblk*8 + g ---
    size_t wro0 = (size_t)(co0 + wid * 8 + g) * K;
    size_t wro1 = (size_t)(co0 + (wid + 8) * 8 + g) * K;

    float2 pa0[4], pa1[4], pb0[4], pb1[4];
    auto loadA = [&](int kk) {
        int kk32 = kk * 32;
        int tap = kk32 / CI, ci0 = kk32 % CI;
        int kh = tap >> 2, kw = tap & 3;
        int hi0 = hb0 + kh, wi0 = wb0 + kw;
        int hi1 = hb1 + kh, wi1 = wb1 + kw;
        bool ok0 = (unsigned)hi0 < (unsigned)HI && (unsigned)wi0 < (unsigned)WI;
        bool ok1 = (unsigned)hi1 < (unsigned)HI && (unsigned)wi1 < (unsigned)WI;
        const float* p0 = in + ab0 + ((size_t)hi0 * WI + wi0) * CI + ci0;
        const float* p1 = in + ab1 + ((size_t)hi1 * WI + wi1) * CI + ci0;
        float2 z = make_float2(0.f, 0.f);
#pragma unroll
        for (int s = 0; s < 2; s++)
#pragma unroll
            for (int p = 0; p < 2; p++) {
                int off = s * 16 + 2 * t + 8 * p;
                pa0[s * 2 + p] = ok0 ? __ldg(reinterpret_cast<const float2*>(p0 + off)) : z;
                pa1[s * 2 + p] = ok1 ? __ldg(reinterpret_cast<const float2*>(p1 + off)) : z;
            }
    };
    auto loadB = [&](int kk) {
#pragma unroll
        for (int s = 0; s < 2; s++)
#pragma unroll
            for (int p = 0; p < 2; p++) {
                int off = kk * 32 + s * 16 + 2 * t + 8 * p;
                pb0[s * 2 + p] = __ldg(reinterpret_cast<const float2*>(wT + wro0 + off));
                pb1[s * 2 + p] = __ldg(reinterpret_cast<const float2*>(wT + wro1 + off));
            }
    };
    auto stsAB = [&](int buf) {
        uint32_t* base = bufs + buf * BUF_U32;
        stsA_fp16(base, wid, lane, pa0, pa1);
        stsB_fp16(base, wid, lane, pb0);
        stsB_fp16(base, wid + 8, lane, pb1);
    };

    float acc[4][4][4];
#pragma unroll
    for (int i = 0; i < 4; i++)
#pragma unroll
        for (int j = 0; j < 4; j++)
#pragma unroll
            for (int e = 0; e < 4; e++) acc[i][j][e] = 0.f;

    loadA(0); loadB(0);
    stsAB(0);
    __syncthreads();

    for (int kk = 0; kk < NCH; kk++) {
        if (kk + 1 < NCH) { loadA(kk + 1); loadB(kk + 1); }
        compute_chunk(bufs + (kk & 1) * BUF_U32, wm, wn, lane, acc);
        if (kk + 1 < NCH) stsAB((kk + 1) & 1);
        __syncthreads();
    }

    // epilogue: descale + bias + relu, NHWC store
    const float ds = 1.f / 65536.f;
#pragma unroll
    for (int i = 0; i < 4; i++) {
        int rlo = rowBase + (wm * 4 + i) * 16 + g;
        int rhi = rlo + 8;
#pragma unroll
        for (int j = 0; j < 4; j++) {
            int c = (wn * 4 + j) * 8 + 2 * t;
            float b0 = aux[c], b1 = aux[c + 1];
            float2 v0 = make_float2(fmaxf(acc[i][j][0] * ds + b0, 0.f),
                                    fmaxf(acc[i][j][1] * ds + b1, 0.f));
            float2 v1 = make_float2(fmaxf(acc[i][j][2] * ds + b0, 0.f),
                                    fmaxf(acc[i][j][3] * ds + b1, 0.f));
            *reinterpret_cast<float2*>(out + (size_t)rlo * CO + co0 + c) = v0;
            *reinterpret_cast<float2*>(out + (size_t)rhi * CO + co0 + c) = v1;
        }
    }
}

// ===========================================================================
// Tensor-core VQ: S = zf(8192x256) @ cb^T; d = ||c||^2 - 2S; row argmin.
// ===========================================================================
__global__ __launch_bounds__(256) void vq_mma(const float* __restrict__ zf,
                                              const float* __restrict__ cb) {
    constexpr int NCH = 8;   // K = 256
    extern __shared__ __align__(16) float smem[];
    float* aux = smem;
    uint32_t* bufs = reinterpret_cast<uint32_t*>(smem + 128);
    __shared__ unsigned long long smin[128];

    int tid = threadIdx.x, lane = tid & 31, wid = tid >> 5;
    int wm = wid >> 2, wn = wid & 3;
    int g = lane >> 2, t = lane & 3;
    int colBase = blockIdx.x * 128;
    int rowBase = blockIdx.y * 128;

    if (tid < 128) { aux[tid] = g_cbnorm[colBase + tid]; smin[tid] = ~0ULL; }

    const float* pA0 = zf + (size_t)(rowBase + wid * 16 + g) * 256;
    const float* pA1 = pA0 + 8 * 256;
    const float* pB0 = cb + (size_t)(colBase + wid * 8 + g) * 256;
    const float* pB1 = cb + (size_t)(colBase + (wid + 8) * 8 + g) * 256;

    float2 pa0[4], pa1[4], pb0[4], pb1[4];
    auto loadAB = [&](int kk) {
#pragma unroll
        for (int s = 0; s < 2; s++)
#pragma unroll
            for (int p = 0; p < 2; p++) {
                int off = kk * 32 + s * 16 + 2 * t + 8 * p;
                pa0[s * 2 + p] = __ldg(reinterpret_cast<const float2*>(pA0 + off));
                pa1[s * 2 + p] = __ldg(reinterpret_cast<const float2*>(pA1 + off));
                pb0[s * 2 + p] = __ldg(reinterpret_cast<const float2*>(pB0 + off));
                pb1[s * 2 + p] = __ldg(reinterpret_cast<const float2*>(pB1 + off));
            }
    };
    auto stsAB = [&](int buf) {
        uint32_t* base = bufs + buf * BUF_U32;
        stsA_fp16(base, wid, lane, pa0, pa1);
        stsB_fp16(base, wid, lane, pb0);
        stsB_fp16(base, wid + 8, lane, pb1);
    };

    float acc[4][4][4];
#pragma unroll
    for (int i = 0; i < 4; i++)
#pragma unroll
        for (int j = 0; j < 4; j++)
#pragma unroll
            for (int e = 0; e < 4; e++) acc[i][j][e] = 0.f;

    loadAB(0);
    stsAB(0);
    __syncthreads();

    for (int kk = 0; kk < NCH; kk++) {
        if (kk + 1 < NCH) loadAB(kk + 1);
        compute_chunk(bufs + (kk & 1) * BUF_U32, wm, wn, lane, acc);
        if (kk + 1 < NCH) stsAB((kk + 1) & 1);
        __syncthreads();
    }

    // argmin epilogue: d = cbnorm - 2 * acc / 65536
    const float ds2 = 2.f / 65536.f;
#pragma unroll
    for (int i = 0; i < 4; i++) {
        int rlo = (wm * 4 + i) * 16 + g;
        float bestl = __int_as_float(0x7f800000); int bcl = 0;
        float besth = __int_as_float(0x7f800000); int bch = 0;
#pragma unroll
        for (int j = 0; j < 4; j++) {
            int c = (wn * 4 + j) * 8 + 2 * t;
            float n0 = aux[c], n1 = aux[c + 1];
            float d0 = n0 - ds2 * acc[i][j][0];
            float d1 = n1 - ds2 * acc[i][j][1];
            float d2 = n0 - ds2 * acc[i][j][2];
            float d3 = n1 - ds2 * acc[i][j][3];
            if (d0 < bestl) { bestl = d0; bcl = c; }
            if (d1 < bestl) { bestl = d1; bcl = c + 1; }
            if (d2 < besth) { besth = d2; bch = c; }
            if (d3 < besth) { besth = d3; bch = c + 1; }
        }
        unsigned ul = __float_as_uint(bestl);
        ul ^= (ul & 0x80000000u) ? 0xFFFFFFFFu : 0x80000000u;
        unsigned uh = __float_as_uint(besth);
        uh ^= (uh & 0x80000000u) ? 0xFFFFFFFFu : 0x80000000u;
        atomicMin(&smin[rlo], ((unsigned long long)ul << 32) | (unsigned)(colBase + bcl));
        atomicMin(&smin[rlo + 8], ((unsigned long long)uh << 32) | (unsigned)(colBase + bch));
    }
    __syncthreads();
    if (tid < 128) atomicMin(&g_min[rowBase + tid], smin[tid]);
}

// ===========================================================================
// cbnorm (warp per code row, fused g_min init) / gather
// ===========================================================================
__global__ void cbnorm_kernel(const float* __restrict__ cb) {
    int w = (blockIdx.x * 256 + threadIdx.x) >> 5;   // 8192 warps
    int lane = threadIdx.x & 31;
    const float4* p = reinterpret_cast<const float4*>(cb + (size_t)w * 256);
    float4 v0 = __ldg(p + lane);
    float4 v1 = __ldg(p + lane + 32);
    float s = v0.x * v0.x + v0.y * v0.y + v0.z * v0.z + v0.w * v0.w
            + v1.x * v1.x + v1.y * v1.y + v1.z * v1.z + v1.w * v1.w;
#pragma unroll
    for (int o = 16; o > 0; o >>= 1) s += __shfl_xor_sync(0xFFFFFFFFu, s, o);
    if (lane == 0) { g_cbnorm[w] = s; g_min[w] = ~0ULL; }
}

__global__ void gather_kernel(const float* __restrict__ cb,
                              float* __restrict__ out,
                              int write_zq, int write_idx, long idx_off) {
    int row = blockIdx.x;
    int c = threadIdx.x;
    unsigned idx = (unsigned)(g_min[row] & 0xFFFFFFFFu);
    if (write_zq) {
        float v = __ldg(cb + (size_t)idx * 256 + c);
        int n = row >> 8;
        int p = row & 255;
        out[(size_t)n * 65536 + (size_t)c * 256 + p] = v;
    }
    if (write_idx && c == 0) out[idx_off + row] = (float)idx;
}

// ===========================================================================
// Launch
// ===========================================================================
extern "C" void kernel_launch(void* const* d_in, const int* in_sizes, int n_in,
                              void* d_out, int out_size) {
    const float* x  = (const float*)d_in[0];
    const float* w1 = (const float*)d_in[1];
    const float* b1 = (const float*)d_in[2];
    const float* w2 = (const float*)d_in[3];
    const float* b2 = (const float*)d_in[4];
    const float* w3 = (const float*)d_in[5];
    const float* b3 = (const float*)d_in[6];
    const float* w4 = (const float*)d_in[7];
    const float* b4 = (const float*)d_in[8];
    const float* cb = (const float*)d_in[9];
    float* out = (float*)d_out;

    float* a1;  cudaGetSymbolAddress((void**)&a1,  g_a1);
    float* a2;  cudaGetSymbolAddress((void**)&a2,  g_a2);
    float* a3;  cudaGetSymbolAddress((void**)&a3,  g_a3);
    float* zf;  cudaGetSymbolAddress((void**)&zf,  g_zf);
    float* wt2; cudaGetSymbolAddress((void**)&wt2, g_wt2);
    float* wt3; cudaGetSymbolAddress((void**)&wt3, g_wt3);
    float* wt4; cudaGetSymbolAddress((void**)&wt4, g_wt4);

    static int attr_done = 0;
    if (!attr_done) {
        cudaFuncSetAttribute(conv_mma<64, 128, 128, 128>, cudaFuncAttributeMaxDynamicSharedMemorySize, GEMM_SMEM);
        cudaFuncSetAttribute(conv_mma<128, 256, 64, 64>, cudaFuncAttributeMaxDynamicSharedMemorySize, GEMM_SMEM);
        cudaFuncSetAttribute(conv_mma<256, 256, 32, 32>, cudaFuncAttributeMaxDynamicSharedMemorySize, GEMM_SMEM);
        cudaFuncSetAttribute(vq_mma, cudaFuncAttributeMaxDynamicSharedMemorySize, GEMM_SMEM);
        attr_done = 1;
    }

    // weight transposes + codebook norms (tiny)
    wtrans_kernel<<<(128 * 1024 + 255) / 256, 256>>>(w2, wt2, 64, 128);
    wtrans_kernel<<<(256 * 2048 + 255) / 256, 256>>>(w3, wt3, 128, 256);
    wtrans_kernel<<<(256 * 4096 + 255) / 256, 256>>>(w4, wt4, 256, 256);
    cbnorm_kernel<<<1024, 256>>>(cb);

    // conv chain (NHWC)
    conv1_nhwc<<<4096, 256>>>(x, w1, b1, a1);
    conv_mma<64, 128, 128, 128><<<dim3(1024, 1), 256, GEMM_SMEM>>>(a1, wt2, b2, a2);
    conv_mma<128, 256, 64, 64><<<dim3(256, 2), 256, GEMM_SMEM>>>(a2, wt3, b3, a3);
    conv_mma<256, 256, 32, 32><<<dim3(64, 2), 256, GEMM_SMEM>>>(a3, wt4, b4, zf);

    // VQ
    vq_mma<<<dim3(64, 64), 256, GEMM_SMEM>>>(zf, cb);

    // output: [z_q (2,097,152 floats)] [idx (8,192, cast to float)]
    const long ZQ = 2097152;
    int write_zq = 0, write_idx = 0; long idx_off = 0;
    if (out_size >= (int)(ZQ + 8192)) { write_zq = 1; write_idx = 1; idx_off = ZQ; }
    else if (out_size >= (int)ZQ)     { write_zq = 1; }
    else                              { write_idx = 1; idx_off = 0; }

    gather_kernel<<<8192, 256>>>(cb, out, write_zq, write_idx, idx_off);
}

// round 11
// speedup vs baseline: 1.7541x; 1.0612x over previous
#include <cuda_runtime.h>
#include <cuda_fp16.h>
#include <cstdint>

// ===========================================================================
// Scratch (__device__ globals; no allocation allowed)
// Split format: uint2 { hi_half2, lo_half2 } covering 2 consecutive channels,
// value v stored as hi+lo = 256*v (fp16 pair), consumed by fp16x2 MMA scheme.
// ===========================================================================
__device__ uint2 g_a1s[32u * 128u * 128u * 64u / 2];   // conv1 out split NHWC
__device__ uint2 g_a2s[32u * 64u * 64u * 128u / 2];
__device__ uint2 g_a3s[32u * 32u * 32u * 256u / 2];
__device__ uint2 g_zfs[8192u * 256u / 2];              // conv4 out split == zf
__device__ uint2 g_wt2s[128u * 1024u / 2];             // weights split [co][tap*CI+ci]
__device__ uint2 g_wt3s[256u * 2048u / 2];
__device__ uint2 g_wt4s[256u * 4096u / 2];
__device__ uint2 g_cbs[8192u * 256u / 2];              // codebook split
__device__ float g_cbnorm[8192];
__device__ unsigned long long g_min[8192];

// ===========================================================================
// Split helpers (epilogue/pre-pass only; mainloop has zero ALU)
// ===========================================================================
__device__ __forceinline__ uint32_t packh2(__half x, __half y) {
    __half2 h = __halves2half2(x, y);
    return *reinterpret_cast<uint32_t*>(&h);
}
__device__ __forceinline__ uint2 splitpk(float x, float y) {
    float sx = x * 256.f, sy = y * 256.f;
    __half hx = __float2half_rn(sx), hy = __float2half_rn(sy);
    float rx = sx - __half2float(hx), ry = sy - __half2float(hy);
    uint2 r;
    r.x = packh2(hx, hy);
    r.y = packh2(__float2half_rn(rx), __float2half_rn(ry));
    return r;
}

__device__ __forceinline__ void mma16(float* d, const uint32_t* a, const uint32_t* b) {
    asm volatile(
        "mma.sync.aligned.m16n8k16.row.col.f32.f16.f16.f32 "
        "{%0,%1,%2,%3}, {%4,%5,%6,%7}, {%8,%9}, {%0,%1,%2,%3};"
        : "+f"(d[0]), "+f"(d[1]), "+f"(d[2]), "+f"(d[3])
        : "r"(a[0]), "r"(a[1]), "r"(a[2]), "r"(a[3]), "r"(b[0]), "r"(b[1]));
}

// SMEM buffer (u32 units): AH[2048] AL[2048] BH[2048] BL[2048] = 8192 u32 = 32KB.
static constexpr int BUF_U32 = 8192;
static constexpr int GEMM_SMEM = 128 * 4 + 2 * BUF_U32 * 4;   // 66048 bytes

// Compute one K=32 chunk. Warp tile 64x32 (4 m-blocks x 4 n-blocks), 8 warps 2x4.
__device__ __forceinline__ void compute_chunk(const uint32_t* buf, int wm, int wn, int lane,
                                              float acc[4][4][4]) {
    const uint32_t* AH = buf;
    const uint32_t* AL = buf + 2048;
    const uint32_t* BH = buf + 4096;
    const uint32_t* BL = buf + 6144;
#pragma unroll
    for (int s = 0; s < 2; s++) {
        uint4 ah[4], al[4];
        uint2 bh[4], bl[4];
#pragma unroll
        for (int i = 0; i < 4; i++) {
            int idx = ((s * 8 + wm * 4 + i) * 32 + lane) * 4;
            ah[i] = *reinterpret_cast<const uint4*>(AH + idx);
            al[i] = *reinterpret_cast<const uint4*>(AL + idx);
        }
#pragma unroll
        for (int j = 0; j < 4; j++) {
            int idx = ((s * 16 + wn * 4 + j) * 32 + lane) * 2;
            bh[j] = *reinterpret_cast<const uint2*>(BH + idx);
            bl[j] = *reinterpret_cast<const uint2*>(BL + idx);
        }
#pragma unroll
        for (int i = 0; i < 4; i++)
#pragma unroll
            for (int j = 0; j < 4; j++) {
                mma16(acc[i][j], &ah[i].x, &bh[j].x);
                mma16(acc[i][j], &al[i].x, &bh[j].x);
                mma16(acc[i][j], &ah[i].x, &bl[j].x);
            }
    }
}

// Fill stores: pa0/pa1 = rows g,g+8, [s*2+p] uint2 pairs; pure register packing.
__device__ __forceinline__ void stsA_pk(uint32_t* base, int mblk, int lane,
                                        const uint2* pa0, const uint2* pa1) {
#pragma unroll
    for (int s = 0; s < 2; s++) {
        uint4 h = make_uint4(pa0[s * 2 + 0].x, pa1[s * 2 + 0].x, pa0[s * 2 + 1].x, pa1[s * 2 + 1].x);
        uint4 l = make_uint4(pa0[s * 2 + 0].y, pa1[s * 2 + 0].y, pa0[s * 2 + 1].y, pa1[s * 2 + 1].y);
        int idx = ((s * 8 + mblk) * 32 + lane) * 4;
        *reinterpret_cast<uint4*>(base + idx) = h;
        *reinterpret_cast<uint4*>(base + 2048 + idx) = l;
    }
}
__device__ __forceinline__ void stsB_pk(uint32_t* base, int nblk, int lane, const uint2* pb) {
#pragma unroll
    for (int s = 0; s < 2; s++) {
        uint2 h = make_uint2(pb[s * 2 + 0].x, pb[s * 2 + 1].x);
        uint2 l = make_uint2(pb[s * 2 + 0].y, pb[s * 2 + 1].y);
        int idx = ((s * 16 + nblk) * 32 + lane) * 2;
        *reinterpret_cast<uint2*>(base + 4096 + idx) = h;
        *reinterpret_cast<uint2*>(base + 6144 + idx) = l;
    }
}

// ===========================================================================
// Weight transpose + split: w[co][ci][kh][kw] -> wTs[(co*K + t*CI+ci)/2] uint2
// ===========================================================================
__global__ void wtrans_kernel(const float* __restrict__ w, uint2* __restrict__ wTs,
                              int CI, int CO) {
    int id = blockIdx.x * 256 + threadIdx.x;
    int K = CI * 16;
    if (id >= CO * K / 2) return;
    int co = id / (K / 2);
    int r2 = id % (K / 2);
    int k0 = 2 * r2, k1 = k0 + 1;
    int tap0 = k0 / CI, ci0 = k0 % CI;
    int tap1 = k1 / CI, ci1 = k1 % CI;
    float v0 = w[(co * CI + ci0) * 16 + tap0];
    float v1 = w[(co * CI + ci1) * 16 + tap1];
    wTs[id] = splitpk(v0, v1);
}

// ===========================================================================
// Conv1: CI=3, k=4 s=2 p=1 + bias + ReLU. NCHW in -> split NHWC out.
// ===========================================================================
__global__ __launch_bounds__(256) void conv1_nhwc(const float* __restrict__ x,
                                                  const float* __restrict__ w,
                                                  const float* __restrict__ b,
                                                  uint2* __restrict__ outs) {
    __shared__ __align__(16) float ws[48][64];
    __shared__ float sb[64];
    int tid = threadIdx.x;
    for (int i = tid; i < 3072; i += 256) {
        int tap = i >> 6, co = i & 63;
        ws[tap][co] = w[co * 48 + tap];
    }
    if (tid < 64) sb[tid] = b[tid];
    __syncthreads();

    int p = blockIdx.x * 128 + (tid >> 1);
    int half = tid & 1;
    int n = p >> 14;
    int rp = p & 16383;
    int ho = rp >> 7, wo = rp & 127;
    int hb = 2 * ho - 1, wb = 2 * wo - 1;
    const float* xb = x + (size_t)n * 3 * 65536;

    float acc[32];
#pragma unroll
    for (int c = 0; c < 32; c++) acc[c] = sb[half * 32 + c];

    for (int ci = 0; ci < 3; ci++) {
        const float* xc = xb + ci * 65536;
        for (int kh = 0; kh < 4; kh++) {
            int hi = hb + kh;
            if ((unsigned)hi >= 256u) continue;
            const float* xr = xc + hi * 256;
            for (int kw = 0; kw < 4; kw++) {
                int wi = wb + kw;
                if ((unsigned)wi >= 256u) continue;
                float v = __ldg(xr + wi);
                const float4* wr = reinterpret_cast<const float4*>(&ws[ci * 16 + kh * 4 + kw][half * 32]);
#pragma unroll
                for (int c4 = 0; c4 < 8; c4++) {
                    float4 wv = wr[c4];
                    acc[c4 * 4 + 0] = fmaf(v, wv.x, acc[c4 * 4 + 0]);
                    acc[c4 * 4 + 1] = fmaf(v, wv.y, acc[c4 * 4 + 1]);
                    acc[c4 * 4 + 2] = fmaf(v, wv.z, acc[c4 * 4 + 2]);
                    acc[c4 * 4 + 3] = fmaf(v, wv.w, acc[c4 * 4 + 3]);
                }
            }
        }
    }
    uint2* op = outs + ((size_t)p * 64 + half * 32) / 2;
#pragma unroll
    for (int c2 = 0; c2 < 16; c2++)
        op[c2] = splitpk(fmaxf(acc[c2 * 2 + 0], 0.f), fmaxf(acc[c2 * 2 + 1], 0.f));
}

// ===========================================================================
// Tensor-core implicit-GEMM conv (k=4 s=2 p=1) + bias + ReLU.
// split NHWC in -> split NHWC out. Block 128x128, K=CI*16 by 32; 8 warps 64x32.
// Mainloop: LDG(uint2) -> STS -> LDS -> MMA. No ALU.
// ===========================================================================
template <int CI, int CO, int HI, int WI>
__global__ __launch_bounds__(256) void conv_mma(const uint2* __restrict__ in,
                                                const uint2* __restrict__ wTs,
                                                const float* __restrict__ bias,
                                                uint2* __restrict__ outs) {
    constexpr int HO = HI / 2, WO = WI / 2;
    constexpr int K = CI * 16;
    constexpr int NCH = K / 32;
    extern __shared__ __align__(16) float smem[];
    float* aux = smem;
    uint32_t* bufs = reinterpret_cast<uint32_t*>(smem + 128);

    int tid = threadIdx.x, lane = tid & 31, wid = tid >> 5;
    int wm = wid >> 2, wn = wid & 3;
    int g = lane >> 2, t = lane & 3;
    int rowBase = blockIdx.x * 128;
    int co0 = blockIdx.y * 128;

    if (tid < 128) aux[tid] = bias[co0 + tid];

    // --- A fill: warp wid = m-block; rows g and g+8 ---
    int rA0 = rowBase + wid * 16 + g;
    int rA1 = rA0 + 8;
    int n0 = rA0 / (HO * WO), rp0 = rA0 % (HO * WO);
    int n1 = rA1 / (HO * WO), rp1 = rA1 % (HO * WO);
    int hb0 = 2 * (rp0 / WO) - 1, wb0 = 2 * (rp0 % WO) - 1;
    int hb1 = 2 * (rp1 / WO) - 1, wb1 = 2 * (rp1 % WO) - 1;
    size_t ab0 = (size_t)n0 * HI * WI * CI;
    size_t ab1 = (size_t)n1 * HI * WI * CI;

    // --- B fill: warp wid covers n-blocks wid, wid+8; col = nblk*8 + g ---
    size_t wb0i = ((size_t)(co0 + wid * 8 + g) * K) >> 1;
    size_t wb1i = ((size_t)(co0 + (wid + 8) * 8 + g) * K) >> 1;

    uint2 pa0[4], pa1[4], pb0[4], pb1[4];
    auto loadA = [&](int kk) {
        int kk32 = kk * 32;
        int tap = kk32 / CI, ci0 = kk32 % CI;
        int kh = tap >> 2, kw = tap & 3;
        int hi0 = hb0 + kh, wi0 = wb0 + kw;
        int hi1 = hb1 + kh, wi1 = wb1 + kw;
        bool ok0 = (unsigned)hi0 < (unsigned)HI && (unsigned)wi0 < (unsigned)WI;
        bool ok1 = (unsigned)hi1 < (unsigned)HI && (unsigned)wi1 < (unsigned)WI;
        size_t b0 = (ab0 + ((size_t)hi0 * WI + wi0) * CI + ci0) >> 1;
        size_t b1 = (ab1 + ((size_t)hi1 * WI + wi1) * CI + ci0) >> 1;
        uint2 z = make_uint2(0u, 0u);
#pragma unroll
        for (int s = 0; s < 2; s++)
#pragma unroll
            for (int p = 0; p < 2; p++) {
                int off = s * 8 + t + 4 * p;
                pa0[s * 2 + p] = ok0 ? __ldg(in + b0 + off) : z;
                pa1[s * 2 + p] = ok1 ? __ldg(in + b1 + off) : z;
            }
    };
    auto loadB = [&](int kk) {
#pragma unroll
        for (int s = 0; s < 2; s++)
#pragma unroll
            for (int p = 0; p < 2; p++) {
                int off = kk * 16 + s * 8 + t + 4 * p;
                pb0[s * 2 + p] = __ldg(wTs + wb0i + off);
                pb1[s * 2 + p] = __ldg(wTs + wb1i + off);
            }
    };
    auto stsAB = [&](int buf) {
        uint32_t* base = bufs + buf * BUF_U32;
        stsA_pk(base, wid, lane, pa0, pa1);
        stsB_pk(base, wid, lane, pb0);
        stsB_pk(base, wid + 8, lane, pb1);
    };

    float acc[4][4][4];
#pragma unroll
    for (int i = 0; i < 4; i++)
#pragma unroll
        for (int j = 0; j < 4; j++)
#pragma unroll
            for (int e = 0; e < 4; e++) acc[i][j][e] = 0.f;

    loadA(0); loadB(0);
    stsAB(0);
    __syncthreads();

    for (int kk = 0; kk < NCH; kk++) {
        if (kk + 1 < NCH) { loadA(kk + 1); loadB(kk + 1); }
        compute_chunk(bufs + (kk & 1) * BUF_U32, wm, wn, lane, acc);
        if (kk + 1 < NCH) stsAB((kk + 1) & 1);
        __syncthreads();
    }

    // epilogue: descale + bias + relu, split store
    const float ds = 1.f / 65536.f;
#pragma unroll
    for (int i = 0; i < 4; i++) {
        int rlo = rowBase + (wm * 4 + i) * 16 + g;
        int rhi = rlo + 8;
#pragma unroll
        for (int j = 0; j < 4; j++) {
            int c = (wn * 4 + j) * 8 + 2 * t;
            float b0 = aux[c], b1 = aux[c + 1];
            outs[((size_t)rlo * CO + co0 + c) >> 1] =
                splitpk(fmaxf(acc[i][j][0] * ds + b0, 0.f), fmaxf(acc[i][j][1] * ds + b1, 0.f));
            outs[((size_t)rhi * CO + co0 + c) >> 1] =
                splitpk(fmaxf(acc[i][j][2] * ds + b0, 0.f), fmaxf(acc[i][j][3] * ds + b1, 0.f));
        }
    }
}

// ===========================================================================
// Tensor-core VQ: S = zf @ cb^T; d = ||c||^2 - 2S; row argmin. Split inputs.
// ===========================================================================
__global__ __launch_bounds__(256) void vq_mma(const uint2* __restrict__ zfs,
                                              const uint2* __restrict__ cbs) {
    constexpr int NCH = 8;   // K = 256
    extern __shared__ __align__(16) float smem[];
    float* aux = smem;
    uint32_t* bufs = reinterpret_cast<uint32_t*>(smem + 128);
    __shared__ unsigned long long smin[128];

    int tid = threadIdx.x, lane = tid & 31, wid = tid >> 5;
    int wm = wid >> 2, wn = wid & 3;
    int g = lane >> 2, t = lane & 3;
    int colBase = blockIdx.x * 128;
    int rowBase = blockIdx.y * 128;

    if (tid < 128) { aux[tid] = g_cbnorm[colBase + tid]; smin[tid] = ~0ULL; }

    size_t a0i = ((size_t)(rowBase + wid * 16 + g) * 256) >> 1;
    size_t a1i = a0i + 4 * 256 / 2 * 2;   // +8 rows: 8*256/2 = 1024
    a1i = a0i + 1024;
    size_t b0i = ((size_t)(colBase + wid * 8 + g) * 256) >> 1;
    size_t b1i = ((size_t)(colBase + (wid + 8) * 8 + g) * 256) >> 1;

    uint2 pa0[4], pa1[4], pb0[4], pb1[4];
    auto loadAB = [&](int kk) {
#pragma unroll
        for (int s = 0; s < 2; s++)
#pragma unroll
            for (int p = 0; p < 2; p++) {
                int off = kk * 16 + s * 8 + t + 4 * p;
                pa0[s * 2 + p] = __ldg(zfs + a0i + off);
                pa1[s * 2 + p] = __ldg(zfs + a1i + off);
                pb0[s * 2 + p] = __ldg(cbs + b0i + off);
                pb1[s * 2 + p] = __ldg(cbs + b1i + off);
            }
    };
    auto stsAB = [&](int buf) {
        uint32_t* base = bufs + buf * BUF_U32;
        stsA_pk(base, wid, lane, pa0, pa1);
        stsB_pk(base, wid, lane, pb0);
        stsB_pk(base, wid + 8, lane, pb1);
    };

    float acc[4][4][4];
#pragma unroll
    for (int i = 0; i < 4; i++)
#pragma unroll
        for (int j = 0; j < 4; j++)
#pragma unroll
            for (int e = 0; e < 4; e++) acc[i][j][e] = 0.f;

    loadAB(0);
    stsAB(0);
    __syncthreads();

    for (int kk = 0; kk < NCH; kk++) {
        if (kk + 1 < NCH) loadAB(kk + 1);
        compute_chunk(bufs + (kk & 1) * BUF_U32, wm, wn, lane, acc);
        if (kk + 1 < NCH) stsAB((kk + 1) & 1);
        __syncthreads();
    }

    // argmin epilogue: d = cbnorm - 2 * acc / 65536
    const float ds2 = 2.f / 65536.f;
#pragma unroll
    for (int i = 0; i < 4; i++) {
        int rlo = (wm * 4 + i) * 16 + g;
        float bestl = __int_as_float(0x7f800000); int bcl = 0;
        float besth = __int_as_float(0x7f800000); int bch = 0;
#pragma unroll
        for (int j = 0; j < 4; j++) {
            int c = (wn * 4 + j) * 8 + 2 * t;
            float n0 = aux[c], n1 = aux[c + 1];
            float d0 = n0 - ds2 * acc[i][j][0];
            float d1 = n1 - ds2 * acc[i][j][1];
            float d2 = n0 - ds2 * acc[i][j][2];
            float d3 = n1 - ds2 * acc[i][j][3];
            if (d0 < bestl) { bestl = d0; bcl = c; }
            if (d1 < bestl) { bestl = d1; bcl = c + 1; }
            if (d2 < besth) { besth = d2; bch = c; }
            if (d3 < besth) { besth = d3; bch = c + 1; }
        }
        unsigned ul = __float_as_uint(bestl);
        ul ^= (ul & 0x80000000u) ? 0xFFFFFFFFu : 0x80000000u;
        unsigned uh = __float_as_uint(besth);
        uh ^= (uh & 0x80000000u) ? 0xFFFFFFFFu : 0x80000000u;
        atomicMin(&smin[rlo], ((unsigned long long)ul << 32) | (unsigned)(colBase + bcl));
        atomicMin(&smin[rlo + 8], ((unsigned long long)uh << 32) | (unsigned)(colBase + bch));
    }
    __syncthreads();
    if (tid < 128) atomicMin(&g_min[rowBase + tid], smin[tid]);
}

// ===========================================================================
// cbnorm: warp per code row; norms + g_min init + split codebook write
// ===========================================================================
__global__ void cbnorm_kernel(const float* __restrict__ cb) {
    int w = (blockIdx.x * 256 + threadIdx.x) >> 5;   // 8192 warps
    int lane = threadIdx.x & 31;
    const float4* p = reinterpret_cast<const float4*>(cb + (size_t)w * 256);
    float4 v0 = __ldg(p + lane);
    float4 v1 = __ldg(p + lane + 32);
    float s = v0.x * v0.x + v0.y * v0.y + v0.z * v0.z + v0.w * v0.w
            + v1.x * v1.x + v1.y * v1.y + v1.z * v1.z + v1.w * v1.w;
    // split writes: channels 4*lane.. and 128+4*lane..
    size_t base = (size_t)w * 128;
    g_cbs[base + 2 * lane + 0] = splitpk(v0.x, v0.y);
    g_cbs[base + 2 * lane + 1] = splitpk(v0.z, v0.w);
    g_cbs[base + 64 + 2 * lane + 0] = splitpk(v1.x, v1.y);
    g_cbs[base + 64 + 2 * lane + 1] = splitpk(v1.z, v1.w);
#pragma unroll
    for (int o = 16; o > 0; o >>= 1) s += __shfl_xor_sync(0xFFFFFFFFu, s, o);
    if (lane == 0) { g_cbnorm[w] = s; g_min[w] = ~0ULL; }
}

__global__ void gather_kernel(const float* __restrict__ cb,
                              float* __restrict__ out,
                              int write_zq, int write_idx, long idx_off) {
    int row = blockIdx.x;
    int c = threadIdx.x;
    unsigned idx = (unsigned)(g_min[row] & 0xFFFFFFFFu);
    if (write_zq) {
        float v = __ldg(cb + (size_t)idx * 256 + c);
        int n = row >> 8;
        int p = row & 255;
        out[(size_t)n * 65536 + (size_t)c * 256 + p] = v;
    }
    if (write_idx && c == 0) out[idx_off + row] = (float)idx;
}

// ===========================================================================
// Launch
// ===========================================================================
extern "C" void kernel_launch(void* const* d_in, const int* in_sizes, int n_in,
                              void* d_out, int out_size) {
    const float* x  = (const float*)d_in[0];
    const float* w1 = (const float*)d_in[1];
    const float* b1 = (const float*)d_in[2];
    const float* w2 = (const float*)d_in[3];
    const float* b2 = (const float*)d_in[4];
    const float* w3 = (const float*)d_in[5];
    const float* b3 = (const float*)d_in[6];
    const float* w4 = (const float*)d_in[7];
    const float* b4 = (const float*)d_in[8];
    const float* cb = (const float*)d_in[9];
    float* out = (float*)d_out;

    uint2* a1s;  cudaGetSymbolAddress((void**)&a1s,  g_a1s);
    uint2* a2s;  cudaGetSymbolAddress((void**)&a2s,  g_a2s);
    uint2* a3s;  cudaGetSymbolAddress((void**)&a3s,  g_a3s);
    uint2* zfs;  cudaGetSymbolAddress((void**)&zfs,  g_zfs);
    uint2* wt2s; cudaGetSymbolAddress((void**)&wt2s, g_wt2s);
    uint2* wt3s; cudaGetSymbolAddress((void**)&wt3s, g_wt3s);
    uint2* wt4s; cudaGetSymbolAddress((void**)&wt4s, g_wt4s);
    uint2* cbs;  cudaGetSymbolAddress((void**)&cbs,  g_cbs);

    static int attr_done = 0;
    if (!attr_done) {
        cudaFuncSetAttribute(conv_mma<64, 128, 128, 128>, cudaFuncAttributeMaxDynamicSharedMemorySize, GEMM_SMEM);
        cudaFuncSetAttribute(conv_mma<128, 256, 64, 64>, cudaFuncAttributeMaxDynamicSharedMemorySize, GEMM_SMEM);
        cudaFuncSetAttribute(conv_mma<256, 256, 32, 32>, cudaFuncAttributeMaxDynamicSharedMemorySize, GEMM_SMEM);
        cudaFuncSetAttribute(vq_mma, cudaFuncAttributeMaxDynamicSharedMemorySize, GEMM_SMEM);
        attr_done = 1;
    }

    // weight transposes (split) + codebook norms/split
    wtrans_kernel<<<(128 * 1024 / 2 + 255) / 256, 256>>>(w2, wt2s, 64, 128);
    wtrans_kernel<<<(256 * 2048 / 2 + 255) / 256, 256>>>(w3, wt3s, 128, 256);
    wtrans_kernel<<<(256 * 4096 / 2 + 255) / 256, 256>>>(w4, wt4s, 256, 256);
    cbnorm_kernel<<<1024, 256>>>(cb);

    // conv chain (split NHWC)
    conv1_nhwc<<<4096, 256>>>(x, w1, b1, a1s);
    conv_mma<64, 128, 128, 128><<<dim3(1024, 1), 256, GEMM_SMEM>>>(a1s, wt2s, b2, a2s);
    conv_mma<128, 256, 64, 64><<<dim3(256, 2), 256, GEMM_SMEM>>>(a2s, wt3s, b3, a3s);
    conv_mma<256, 256, 32, 32><<<dim3(64, 2), 256, GEMM_SMEM>>>(a3s, wt4s, b4, zfs);

    // VQ
    vq_mma<<<dim3(64, 64), 256, GEMM_SMEM>>>(zfs, cbs);

    // output: [z_q (2,097,152 floats)] [idx (8,192, cast to float)]
    const long ZQ = 2097152;
    int write_zq = 0, write_idx = 0; long idx_off = 0;
    if (out_size >= (int)(ZQ + 8192)) { write_zq = 1; write_idx = 1; idx_off = ZQ; }
    else if (out_size >= (int)ZQ)     { write_zq = 1; }
    else                              { write_idx = 1; idx_off = 0; }

    gather_kernel<<<8192, 256>>>(cb, out, write_zq, write_idx, idx_off);
}